// round 4
// baseline (speedup 1.0000x reference)
#include <cuda_runtime.h>

// ---------------- scratch (no allocations allowed) ----------------
#define MAXN 16384
#define MAXE 1048576

__device__ int  g_is64;                // 1 if edge_index is int64, 0 if int32
__device__ int  g_counts[MAXN];
__device__ int  g_offsets[MAXN + 1];
__device__ int  g_rank[MAXE];          // within-bucket rank per edge
__device__ int2 g_pack[MAXE];          // {edge id, source col} per CSR slot

__device__ __forceinline__ int load_idx(const void* p, long i, int is64) {
    if (is64) return (int)(((const long long*)p)[i]);
    return ((const int*)p)[i];
}

// K0: zero counters; block 0 detects int32 vs int64 edge_index.
// int64 node ids < 2^31 => every odd 32-bit word is 0 (256 samples).
__global__ void k0_init(const int* ei_words, int n) {
    for (int i = blockIdx.x * blockDim.x + threadIdx.x; i < n;
         i += gridDim.x * blockDim.x) {
        g_counts[i] = 0;
    }
    if (blockIdx.x == 0) {
        __shared__ int any_nonzero;
        if (threadIdx.x == 0) any_nonzero = 0;
        __syncthreads();
        int w = ei_words[2 * threadIdx.x + 1];
        if (w != 0) atomicOr(&any_nonzero, 1);
        __syncthreads();
        if (threadIdx.x == 0) g_is64 = any_nonzero ? 0 : 1;
    }
}

// K1: histogram of destinations; atomic result IS the within-bucket rank.
__global__ void k1_count(const void* ei, long E) {
    int is64 = g_is64;
    long base = (long)blockIdx.x * (blockDim.x * 4) + threadIdx.x;
    long s = blockDim.x;
    int r[4];
    bool ok[4];
#pragma unroll
    for (int u = 0; u < 4; u++) {
        long i = base + u * s;
        ok[u] = (i < E);
        r[u] = ok[u] ? load_idx(ei, i, is64) : 0;
    }
    int rk[4];
#pragma unroll
    for (int u = 0; u < 4; u++)
        if (ok[u]) rk[u] = atomicAdd(&g_counts[r[u]], 1);
#pragma unroll
    for (int u = 0; u < 4; u++)
        if (ok[u]) g_rank[base + u * s] = rk[u];
}

// K2: chunked single-block exclusive scan. counts -> offsets.
#define SCAN_CHUNK 16
__global__ void k2_scan(int n) {
    const int T = 1024;
    int chunk = (n + T - 1) / T;           // <= SCAN_CHUNK
    int base = threadIdx.x * chunk;
    int local[SCAN_CHUNK];
    int sum = 0;
#pragma unroll
    for (int k = 0; k < SCAN_CHUNK; k++) {
        if (k < chunk) {
            int i = base + k;
            int v = (i < n) ? g_counts[i] : 0;
            local[k] = sum;               // exclusive-within-chunk
            sum += v;
        }
    }
    __shared__ int sh[T];
    sh[threadIdx.x] = sum;
    __syncthreads();
#pragma unroll
    for (int off = 1; off < T; off <<= 1) {
        int t = (threadIdx.x >= off) ? sh[threadIdx.x - off] : 0;
        __syncthreads();
        sh[threadIdx.x] += t;
        __syncthreads();
    }
    int excl_block = sh[threadIdx.x] - sum;
#pragma unroll
    for (int k = 0; k < SCAN_CHUNK; k++) {
        if (k < chunk) {
            int i = base + k;
            if (i < n) g_offsets[i] = excl_block + local[k];
        }
    }
    if (threadIdx.x == T - 1) g_offsets[n] = excl_block + sum;
}

// K3: NO atomics. pos = offsets[r] + rank[i]; offsets (40KB) is L1-resident.
__global__ void k3_fill(const void* ei, long E) {
    int is64 = g_is64;
    long base = (long)blockIdx.x * (blockDim.x * 4) + threadIdx.x;
    long s = blockDim.x;
    int r[4], c[4], rk[4];
    bool ok[4];
#pragma unroll
    for (int u = 0; u < 4; u++) {
        long i = base + u * s;
        ok[u] = (i < E);
        r[u]  = ok[u] ? load_idx(ei, i, is64) : 0;
        c[u]  = ok[u] ? load_idx(ei, E + i, is64) : 0;
        rk[u] = ok[u] ? g_rank[i] : 0;
    }
#pragma unroll
    for (int u = 0; u < 4; u++) {
        if (ok[u]) {
            int pos = g_offsets[r[u]] + rk[u];
            g_pack[pos] = make_int2((int)(base + u * s), c[u]);
        }
    }
}

__device__ __forceinline__ void acc4(float4& a, const float4 v) {
    a.x += v.x; a.y += v.y; a.z += v.z; a.w += v.w;
}

// K4: one block (4 warps) per node.
// warps 0,1: sum of x[col[e]] (gather, L2-resident), bucket strided by 2
// warps 2,3: sum of edge_attr[e] (HBM stream), bucket strided by 2
// partials combined via smem; warp 3 also copies the x row.
__global__ void __launch_bounds__(128) k4_agg(const float* __restrict__ x,
                                              const float* __restrict__ ea,
                                              float* __restrict__ out) {
    __shared__ float4 shp[2][32];

    int n   = blockIdx.x;
    int lid = threadIdx.x & 31;
    int w   = threadIdx.x >> 5;    // 0..3
    int stream = w >> 1;           // 0: x-gather, 1: edge_attr
    int sub    = w & 1;
    int beg = g_offsets[n];
    int end = g_offsets[n + 1];

    float4 a0 = make_float4(0.f, 0.f, 0.f, 0.f);
    float4 a1 = a0, a2 = a0, a3 = a0;

    if (stream == 0) {
        int j = beg + sub;
        for (; j + 6 < end; j += 8) {
            int2 p0 = g_pack[j];
            int2 p1 = g_pack[j + 2];
            int2 p2 = g_pack[j + 4];
            int2 p3 = g_pack[j + 6];
            float4 v0 = __ldg((const float4*)(x + (long)p0.y * 128) + lid);
            float4 v1 = __ldg((const float4*)(x + (long)p1.y * 128) + lid);
            float4 v2 = __ldg((const float4*)(x + (long)p2.y * 128) + lid);
            float4 v3 = __ldg((const float4*)(x + (long)p3.y * 128) + lid);
            acc4(a0, v0); acc4(a1, v1); acc4(a2, v2); acc4(a3, v3);
        }
        for (; j < end; j += 2) {
            int2 p = g_pack[j];
            acc4(a0, __ldg((const float4*)(x + (long)p.y * 128) + lid));
        }
    } else {
        int j = beg + sub;
        for (; j + 6 < end; j += 8) {
            int2 p0 = g_pack[j];
            int2 p1 = g_pack[j + 2];
            int2 p2 = g_pack[j + 4];
            int2 p3 = g_pack[j + 6];
            float4 v0 = __ldcs((const float4*)(ea + (long)p0.x * 128) + lid);
            float4 v1 = __ldcs((const float4*)(ea + (long)p1.x * 128) + lid);
            float4 v2 = __ldcs((const float4*)(ea + (long)p2.x * 128) + lid);
            float4 v3 = __ldcs((const float4*)(ea + (long)p3.x * 128) + lid);
            acc4(a0, v0); acc4(a1, v1); acc4(a2, v2); acc4(a3, v3);
        }
        for (; j < end; j += 2) {
            int2 p = g_pack[j];
            acc4(a0, __ldcs((const float4*)(ea + (long)p.x * 128) + lid));
        }
    }

    float4 s;
    s.x = (a0.x + a1.x) + (a2.x + a3.x);
    s.y = (a0.y + a1.y) + (a2.y + a3.y);
    s.z = (a0.z + a1.z) + (a2.z + a3.z);
    s.w = (a0.w + a1.w) + (a2.w + a3.w);

    if (sub == 1) shp[stream][lid] = s;
    __syncthreads();

    long ob = (long)n * 384;
    if (sub == 0) {
        float4 t = shp[stream][lid];
        int deg = end - beg;
        float inv = 1.0f / (float)(deg > 0 ? deg : 1);
        s.x = (s.x + t.x) * inv;
        s.y = (s.y + t.y) * inv;
        s.z = (s.z + t.z) * inv;
        s.w = (s.w + t.w) * inv;
        // stream 0 -> cols [128,256), stream 1 -> cols [256,384)
        ((float4*)(out + ob + 128 + stream * 128))[lid] = s;
    } else if (w == 3) {
        float4 xv = __ldg((const float4*)(x + (long)n * 128) + lid);
        ((float4*)(out + ob))[lid] = xv;   // out[:,0:128] = x
    }
}

extern "C" void kernel_launch(void* const* d_in, const int* in_sizes, int n_in,
                              void* d_out, int out_size) {
    const float* x  = (const float*)d_in[0];
    const void*  ei = d_in[1];            // edge_index [2,E], int32 or int64
    const float* ea = (const float*)d_in[2];
    float* out = (float*)d_out;

    int  N = in_sizes[0] / 128;           // node count
    long E = (long)in_sizes[1] / 2;       // edge count (dtype-independent)

    const int TB = 256;
    int eb4 = (int)((E + (long)TB * 4 - 1) / ((long)TB * 4));

    k0_init<<<64, TB>>>((const int*)ei, N);
    k1_count<<<eb4, TB>>>(ei, E);
    k2_scan<<<1, 1024>>>(N);
    k3_fill<<<eb4, TB>>>(ei, E);
    k4_agg<<<N, 128>>>(x, ea, out);
}

// round 5
// speedup vs baseline: 1.1459x; 1.1459x over previous
#include <cuda_runtime.h>

// ---------------- scratch (no allocations allowed) ----------------
#define MAXN 16384
#define MAXE 1048576

__device__ int  g_counts[MAXN];        // zero at load; re-zeroed by k3 each call
__device__ int  g_offsets[MAXN + 1];
__device__ int  g_rank[MAXE];          // within-bucket rank per edge
__device__ int2 g_pack[MAXE];          // {edge id, source col} per CSR slot

__device__ __forceinline__ int load_idx(const void* p, long i, int is64) {
    if (is64) return (int)(((const long long*)p)[i]);
    return ((const int*)p)[i];
}

// Per-block int64-vs-int32 detection: int64 ids < 2^31 => odd 32-bit words all 0.
// Samples 128 odd words; identical data => identical verdict in every block.
__device__ __forceinline__ int detect_is64(const int* ei_words) {
    __shared__ int s_nz;
    if (threadIdx.x == 0) s_nz = 0;
    __syncthreads();
    if (threadIdx.x < 128) {
        if (ei_words[2 * threadIdx.x + 1] != 0) atomicOr(&s_nz, 1);
    }
    __syncthreads();
    return s_nz ? 0 : 1;
}

// K1: histogram of destinations; atomic result IS the within-bucket rank.
__global__ void k1_count(const void* ei, long E) {
    int is64 = detect_is64((const int*)ei);
    long base = (long)blockIdx.x * (blockDim.x * 4) + threadIdx.x;
    long s = blockDim.x;
    int r[4];
    bool ok[4];
#pragma unroll
    for (int u = 0; u < 4; u++) {
        long i = base + u * s;
        ok[u] = (i < E);
        r[u] = ok[u] ? load_idx(ei, i, is64) : 0;
    }
    int rk[4];
#pragma unroll
    for (int u = 0; u < 4; u++)
        if (ok[u]) rk[u] = atomicAdd(&g_counts[r[u]], 1);
#pragma unroll
    for (int u = 0; u < 4; u++)
        if (ok[u]) g_rank[base + u * s] = rk[u];
}

// K2: single-block exclusive scan, shuffle-based (2 barriers).
#define SCAN_CHUNK 16
__global__ void k2_scan(int n) {
    const int T = 1024;
    int chunk = (n + T - 1) / T;           // <= SCAN_CHUNK
    int base = threadIdx.x * chunk;
    int local[SCAN_CHUNK];
    int sum = 0;
#pragma unroll
    for (int k = 0; k < SCAN_CHUNK; k++) {
        if (k < chunk) {
            int i = base + k;
            int v = (i < n) ? g_counts[i] : 0;
            local[k] = sum;               // exclusive-within-chunk
            sum += v;
        }
    }
    int lid = threadIdx.x & 31;
    int wid = threadIdx.x >> 5;
    // warp inclusive scan of per-thread sums
    int incl = sum;
#pragma unroll
    for (int off = 1; off < 32; off <<= 1) {
        int t = __shfl_up_sync(0xffffffffu, incl, off);
        if (lid >= off) incl += t;
    }
    __shared__ int warp_tot[32];
    if (lid == 31) warp_tot[wid] = incl;
    __syncthreads();
    if (wid == 0) {
        int v = warp_tot[lid];
        int wi = v;
#pragma unroll
        for (int off = 1; off < 32; off <<= 1) {
            int t = __shfl_up_sync(0xffffffffu, wi, off);
            if (lid >= off) wi += t;
        }
        warp_tot[lid] = wi - v;           // exclusive warp prefix
    }
    __syncthreads();
    int excl_thread = warp_tot[wid] + (incl - sum);  // exclusive prefix of this thread
#pragma unroll
    for (int k = 0; k < SCAN_CHUNK; k++) {
        if (k < chunk) {
            int i = base + k;
            if (i < n) g_offsets[i] = excl_thread + local[k];
        }
    }
    if (threadIdx.x == T - 1) g_offsets[n] = excl_thread + sum;
}

// K3: NO atomics. pos = offsets[r] + rank[i]. Also re-zeroes g_counts for the
// next graph replay (k2 was the last reader; globals are zero at module load,
// so every call of kernel_launch sees zeroed counts).
__global__ void k3_fill(const void* ei, long E) {
    int is64 = detect_is64((const int*)ei);
    long base = (long)blockIdx.x * (blockDim.x * 4) + threadIdx.x;
    long s = blockDim.x;
    int r[4], c[4], rk[4];
    bool ok[4];
#pragma unroll
    for (int u = 0; u < 4; u++) {
        long i = base + u * s;
        ok[u] = (i < E);
        r[u]  = ok[u] ? load_idx(ei, i, is64) : 0;
        c[u]  = ok[u] ? load_idx(ei, E + i, is64) : 0;
        rk[u] = ok[u] ? g_rank[i] : 0;
    }
#pragma unroll
    for (int u = 0; u < 4; u++) {
        if (ok[u]) {
            int pos = g_offsets[r[u]] + rk[u];
            g_pack[pos] = make_int2((int)(base + u * s), c[u]);
        }
    }
    int gid = blockIdx.x * blockDim.x + threadIdx.x;
    if (gid < MAXN) g_counts[gid] = 0;
}

__device__ __forceinline__ void acc4(float4& a, const float4 v) {
    a.x += v.x; a.y += v.y; a.z += v.z; a.w += v.w;
}

// K4 (R3-proven form): one block (2 warps) per node.
// warp 0: sum of x[col[e]] (gather, L2-resident) + copy x row
// warp 1: sum of edge_attr[e] (HBM stream, streaming hint)
__global__ void __launch_bounds__(64) k4_agg(const float* __restrict__ x,
                                             const float* __restrict__ ea,
                                             float* __restrict__ out) {
    int n   = blockIdx.x;
    int lid = threadIdx.x & 31;
    int w   = threadIdx.x >> 5;
    int beg = g_offsets[n];
    int end = g_offsets[n + 1];

    float4 a0 = make_float4(0.f, 0.f, 0.f, 0.f);
    float4 a1 = a0, a2 = a0, a3 = a0;

    if (w == 0) {
        int j = beg;
        for (; j + 4 <= end; j += 4) {
            int2 p0 = g_pack[j];
            int2 p1 = g_pack[j + 1];
            int2 p2 = g_pack[j + 2];
            int2 p3 = g_pack[j + 3];
            float4 v0 = __ldg((const float4*)(x + (long)p0.y * 128) + lid);
            float4 v1 = __ldg((const float4*)(x + (long)p1.y * 128) + lid);
            float4 v2 = __ldg((const float4*)(x + (long)p2.y * 128) + lid);
            float4 v3 = __ldg((const float4*)(x + (long)p3.y * 128) + lid);
            acc4(a0, v0); acc4(a1, v1); acc4(a2, v2); acc4(a3, v3);
        }
        for (; j < end; ++j) {
            int2 p = g_pack[j];
            acc4(a0, __ldg((const float4*)(x + (long)p.y * 128) + lid));
        }
    } else {
        int j = beg;
        for (; j + 4 <= end; j += 4) {
            int2 p0 = g_pack[j];
            int2 p1 = g_pack[j + 1];
            int2 p2 = g_pack[j + 2];
            int2 p3 = g_pack[j + 3];
            float4 v0 = __ldcs((const float4*)(ea + (long)p0.x * 128) + lid);
            float4 v1 = __ldcs((const float4*)(ea + (long)p1.x * 128) + lid);
            float4 v2 = __ldcs((const float4*)(ea + (long)p2.x * 128) + lid);
            float4 v3 = __ldcs((const float4*)(ea + (long)p3.x * 128) + lid);
            acc4(a0, v0); acc4(a1, v1); acc4(a2, v2); acc4(a3, v3);
        }
        for (; j < end; ++j) {
            int2 p = g_pack[j];
            acc4(a0, __ldcs((const float4*)(ea + (long)p.x * 128) + lid));
        }
    }

    float4 s;
    s.x = (a0.x + a1.x) + (a2.x + a3.x);
    s.y = (a0.y + a1.y) + (a2.y + a3.y);
    s.z = (a0.z + a1.z) + (a2.z + a3.z);
    s.w = (a0.w + a1.w) + (a2.w + a3.w);

    int deg = end - beg;
    float inv = 1.0f / (float)(deg > 0 ? deg : 1);
    s.x *= inv; s.y *= inv; s.z *= inv; s.w *= inv;

    long ob = (long)n * 384;
    if (w == 0) {
        float4 xv = __ldg((const float4*)(x + (long)n * 128) + lid);
        ((float4*)(out + ob))[lid]       = xv;  // out[:,0:128]   = x
        ((float4*)(out + ob + 128))[lid] = s;   // out[:,128:256] = mean x-gather
    } else {
        ((float4*)(out + ob + 256))[lid] = s;   // out[:,256:384] = mean edge_attr
    }
}

extern "C" void kernel_launch(void* const* d_in, const int* in_sizes, int n_in,
                              void* d_out, int out_size) {
    const float* x  = (const float*)d_in[0];
    const void*  ei = d_in[1];            // edge_index [2,E], int32 or int64
    const float* ea = (const float*)d_in[2];
    float* out = (float*)d_out;

    int  N = in_sizes[0] / 128;           // node count
    long E = (long)in_sizes[1] / 2;       // edge count (dtype-independent)

    const int TB = 256;
    int eb4 = (int)((E + (long)TB * 4 - 1) / ((long)TB * 4));

    k1_count<<<eb4, TB>>>(ei, E);
    k2_scan<<<1, 1024>>>(N);
    k3_fill<<<eb4, TB>>>(ei, E);
    k4_agg<<<N, 64>>>(x, ea, out);
}